// round 1
// baseline (speedup 1.0000x reference)
#include <cuda_runtime.h>
#include <math.h>

// Problem constants: B=32, N=128, D=256, H=8, DK=32
#define NB 32
#define NN 128
#define ND 256
#define NH 8
#define NDK 32

// ---------------- scratch (static device globals; no allocation) -------------
__device__ float g_feats[1024 * 256];   // [H*N, D] packed feats
__device__ float g_fA[1024 * 256];      // feats @ W_top
__device__ float g_fB[1024 * 256];      // feats @ W_bot
__device__ float g_conn[8 * 128 * 128]; // hard connection mask (0/1)
__device__ float g_h1[4096 * 256];      // gelu(x@W1+b1)
__device__ float g_xm[4096 * 256];      // mlp out
__device__ float g_q[4096 * 256];       // [B,H,N,DK]
__device__ float g_k[4096 * 256];
__device__ float g_v[4096 * 256];
__device__ float g_ao[4096 * 256];      // attention out, [B,N,D]

__device__ __forceinline__ float gelu_tanh(float x) {
    float x3 = x * x * x;
    float t = tanhf(0.7978845608028654f * (x + 0.044715f * x3));
    return 0.5f * x * (1.0f + t);
}

// ---------------- pack feats: feats[h,n,:] = memory_w[n, h*256 : h*256+256] --
__global__ void k_pack(const float* __restrict__ mw, float* __restrict__ out) {
    int row = blockIdx.x;              // h*128 + n
    int h = row >> 7, n = row & 127;
    int t = threadIdx.x;
    out[row * 256 + t] = mw[n * 2048 + h * 256 + t];
}

// ---------------- generic SGEMM: C[M,256] = A[M,256] @ W[256,256] (+bias)(+gelu)
// 256 threads, BM=BN=64, BK=16, 4x4 per thread.
// store_mode 0: C[row*256+col]; 1: QKV permute -> [B,H,N,DK]
__global__ void k_gemm(const float* __restrict__ A, const float* __restrict__ W,
                       const float* __restrict__ bias, float* __restrict__ C,
                       int act, int store_mode)
{
    __shared__ float As[16][68];  // padded: (k*68+row) -> conflict-light, 16B aligned rows
    __shared__ float Ws[16][64];

    int t = threadIdx.x;
    int tx = t & 15, ty = t >> 4;
    int rowBase = blockIdx.x * 64;
    int colBase = blockIdx.y * 64;

    int lak = t & 15;          // k index for A load
    int lar = (t >> 4) * 4;    // row base for A load
    int lwc = t & 63;          // col for W load
    int lwk = (t >> 6) * 4;    // k base for W load

    float acc[4][4];
    #pragma unroll
    for (int i = 0; i < 4; i++)
        #pragma unroll
        for (int j = 0; j < 4; j++) acc[i][j] = 0.0f;

    for (int kt = 0; kt < 256; kt += 16) {
        #pragma unroll
        for (int i = 0; i < 4; i++)
            As[lak][lar + i] = A[(rowBase + lar + i) * 256 + kt + lak];
        #pragma unroll
        for (int i = 0; i < 4; i++)
            Ws[lwk + i][lwc] = W[(kt + lwk + i) * 256 + colBase + lwc];
        __syncthreads();

        #pragma unroll
        for (int kk = 0; kk < 16; kk++) {
            float4 a = *(const float4*)&As[kk][ty * 4];
            float4 b = *(const float4*)&Ws[kk][tx * 4];
            acc[0][0] = fmaf(a.x, b.x, acc[0][0]);
            acc[0][1] = fmaf(a.x, b.y, acc[0][1]);
            acc[0][2] = fmaf(a.x, b.z, acc[0][2]);
            acc[0][3] = fmaf(a.x, b.w, acc[0][3]);
            acc[1][0] = fmaf(a.y, b.x, acc[1][0]);
            acc[1][1] = fmaf(a.y, b.y, acc[1][1]);
            acc[1][2] = fmaf(a.y, b.z, acc[1][2]);
            acc[1][3] = fmaf(a.y, b.w, acc[1][3]);
            acc[2][0] = fmaf(a.z, b.x, acc[2][0]);
            acc[2][1] = fmaf(a.z, b.y, acc[2][1]);
            acc[2][2] = fmaf(a.z, b.z, acc[2][2]);
            acc[2][3] = fmaf(a.z, b.w, acc[2][3]);
            acc[3][0] = fmaf(a.w, b.x, acc[3][0]);
            acc[3][1] = fmaf(a.w, b.y, acc[3][1]);
            acc[3][2] = fmaf(a.w, b.z, acc[3][2]);
            acc[3][3] = fmaf(a.w, b.w, acc[3][3]);
        }
        __syncthreads();
    }

    #pragma unroll
    for (int i = 0; i < 4; i++) {
        int row = rowBase + ty * 4 + i;
        #pragma unroll
        for (int j = 0; j < 4; j++) {
            int col = colBase + tx * 4 + j;
            float v = acc[i][j];
            if (bias) v += bias[col];
            if (act) v = gelu_tanh(v);
            if (store_mode == 0) {
                C[row * 256 + col] = v;
            } else {
                int b = row >> 7, n = row & 127;
                int h = col >> 5, dk = col & 31;
                C[(((b * 8 + h) * 128 + n) * 32) + dk] = v;
            }
        }
    }
}

// ---------------- connection mask: per (h,i), warp per j ---------------------
// logits[h,i,j,k] = sum_d relu(fA[h,j,d]+fB[h,i,d]+ob[d]) * cw[d,k] + cb[k]
// conn = (l1+g1 > l0+g0)
__global__ void k_conn(const float* __restrict__ fA, const float* __restrict__ fB,
                       const float* __restrict__ ob, const float* __restrict__ cw,
                       const float* __restrict__ cb, const float* __restrict__ gu,
                       float* __restrict__ conn)
{
    int h = blockIdx.x, i = blockIdx.y;
    __shared__ float Bi[256], c0[256], c1[256];
    int t = threadIdx.x;  // 256
    Bi[t] = fB[(h * 128 + i) * 256 + t] + ob[t];
    c0[t] = cw[t * 2 + 0];
    c1[t] = cw[t * 2 + 1];
    __syncthreads();

    int w = t >> 5, lane = t & 31;
    float cb0 = cb[0], cb1 = cb[1];

    for (int j = w; j < 128; j += 8) {
        const float* ar = &fA[(h * 128 + j) * 256];
        float l0 = 0.0f, l1 = 0.0f;
        #pragma unroll
        for (int u = 0; u < 8; u++) {
            int d = lane + 32 * u;
            float r = ar[d] + Bi[d];
            r = fmaxf(r, 0.0f);
            l0 = fmaf(r, c0[d], l0);
            l1 = fmaf(r, c1[d], l1);
        }
        #pragma unroll
        for (int off = 16; off; off >>= 1) {
            l0 += __shfl_xor_sync(0xffffffffu, l0, off);
            l1 += __shfl_xor_sync(0xffffffffu, l1, off);
        }
        if (lane == 0) {
            int gi = ((h * 128 + i) * 128 + j) * 2;
            float u0 = gu[gi + 0], u1 = gu[gi + 1];
            float g0 = -logf(-logf(u0 + 1e-10f) + 1e-10f);
            float g1 = -logf(-logf(u1 + 1e-10f) + 1e-10f);
            conn[(h * 128 + i) * 128 + j] = ((l1 + cb1 + g1) > (l0 + cb0 + g0)) ? 1.0f : 0.0f;
        }
    }
}

// ---------------- masked attention, one block per (b,h), 128 threads ---------
// smem: sc[128][129] scores, kv[128][32] (K then reused for V), cmask[128][4]
#define SC_FLOATS (128 * 129)
#define KV_FLOATS (128 * 32)
#define SMEM_ATTN ((SC_FLOATS + KV_FLOATS) * 4 + 128 * 4 * 4)

__global__ void k_attn(const float* __restrict__ q, const float* __restrict__ k,
                       const float* __restrict__ v, const float* __restrict__ conn,
                       float* __restrict__ ao)
{
    extern __shared__ float sm[];
    float* sc = sm;                       // 128*129
    float* kv = sm + SC_FLOATS;           // 128*32 (16B aligned)
    unsigned* cmask = (unsigned*)(kv + KV_FLOATS);  // 128*4 words

    int bid = blockIdx.x;
    int b = bid >> 3, h = bid & 7;
    int t = threadIdx.x, w = t >> 5, lane = t & 31;

    // build bitmask from conn (coalesced + ballot)
    const float* cr = conn + h * 16384;
    for (int i0 = 0; i0 < 128; i0++) {
        float c = cr[i0 * 128 + t];
        unsigned bal = __ballot_sync(0xffffffffu, c > 0.5f);
        if (lane == 0) cmask[i0 * 4 + w] = bal;
    }

    // stage K
    for (int idx = t; idx < KV_FLOATS; idx += 128) kv[idx] = k[bid * 4096 + idx];
    __syncthreads();

    // q row in registers (float4)
    float4 qr[8];
    const float4* qp = (const float4*)(q + (bid * 128 + t) * 32);
    #pragma unroll
    for (int d = 0; d < 8; d++) qr[d] = qp[d];

    unsigned marr[4];
    #pragma unroll
    for (int u = 0; u < 4; u++) marr[u] = cmask[t * 4 + u];

    const float scale = 0.17677669529663687f;  // 1/sqrt(32)
    const float4* kv4 = (const float4*)kv;
    float mx = -INFINITY;

    for (int wdx = 0; wdx < 4; wdx++) {
        unsigned word = marr[wdx];
        for (int jj = 0; jj < 32; jj++) {
            int j = (wdx << 5) | jj;
            float s;
            if ((word >> jj) & 1u) {
                float a0 = 0.f, a1 = 0.f, a2 = 0.f, a3 = 0.f;
                #pragma unroll
                for (int d = 0; d < 8; d++) {
                    float4 kk4 = kv4[j * 8 + d];
                    a0 = fmaf(qr[d].x, kk4.x, a0);
                    a1 = fmaf(qr[d].y, kk4.y, a1);
                    a2 = fmaf(qr[d].z, kk4.z, a2);
                    a3 = fmaf(qr[d].w, kk4.w, a3);
                }
                s = ((a0 + a1) + (a2 + a3)) * scale;
                mx = fmaxf(mx, s);
            } else {
                s = -INFINITY;
            }
            sc[t * 129 + j] = s;
        }
    }
    __syncthreads();  // all done reading K

    // stage V over K's smem while doing per-row softmax
    for (int idx = t; idx < KV_FLOATS; idx += 128) kv[idx] = v[bid * 4096 + idx];

    float sum = 0.0f;
    for (int j = 0; j < 128; j++) {
        float e = expf(sc[t * 129 + j] - mx);  // masked: exp(-inf)=0
        sum += e;
        sc[t * 129 + j] = e;
    }
    float inv = 1.0f / sum;
    __syncthreads();

    float acc[32];
    #pragma unroll
    for (int d = 0; d < 32; d++) acc[d] = 0.0f;

    for (int j = 0; j < 128; j++) {
        float p = sc[t * 129 + j];
        #pragma unroll
        for (int dd = 0; dd < 8; dd++) {
            float4 vv = kv4[j * 8 + dd];
            acc[dd * 4 + 0] = fmaf(p, vv.x, acc[dd * 4 + 0]);
            acc[dd * 4 + 1] = fmaf(p, vv.y, acc[dd * 4 + 1]);
            acc[dd * 4 + 2] = fmaf(p, vv.z, acc[dd * 4 + 2]);
            acc[dd * 4 + 3] = fmaf(p, vv.w, acc[dd * 4 + 3]);
        }
    }

    float* op = ao + (b * 128 + t) * 256 + h * 32;
    #pragma unroll
    for (int d = 0; d < 32; d++) op[d] = acc[d] * inv;
}

// ---------------- launch ------------------------------------------------------
extern "C" void kernel_launch(void* const* d_in, const int* in_sizes, int n_in,
                              void* d_out, int out_size)
{
    const float* x        = (const float*)d_in[0];
    const float* gumbel_u = (const float*)d_in[1];
    const float* memory_w = (const float*)d_in[2];
    const float* fc_out_w = (const float*)d_in[3];
    const float* fc_out_b = (const float*)d_in[4];
    const float* fc_cat_w = (const float*)d_in[5];
    const float* fc_cat_b = (const float*)d_in[6];
    const float* wq       = (const float*)d_in[7];
    const float* bq       = (const float*)d_in[8];
    const float* wk       = (const float*)d_in[9];
    const float* bk       = (const float*)d_in[10];
    const float* wv       = (const float*)d_in[11];
    const float* bv       = (const float*)d_in[12];
    const float* out_w    = (const float*)d_in[13];
    const float* out_b    = (const float*)d_in[14];
    const float* mlp_w1   = (const float*)d_in[15];
    const float* mlp_b1   = (const float*)d_in[16];
    const float* mlp_w2   = (const float*)d_in[17];
    const float* mlp_b2   = (const float*)d_in[18];

    float *feats, *fA, *fB, *conn, *h1, *xm, *q, *k, *v, *ao;
    cudaGetSymbolAddress((void**)&feats, g_feats);
    cudaGetSymbolAddress((void**)&fA, g_fA);
    cudaGetSymbolAddress((void**)&fB, g_fB);
    cudaGetSymbolAddress((void**)&conn, g_conn);
    cudaGetSymbolAddress((void**)&h1, g_h1);
    cudaGetSymbolAddress((void**)&xm, g_xm);
    cudaGetSymbolAddress((void**)&q, g_q);
    cudaGetSymbolAddress((void**)&k, g_k);
    cudaGetSymbolAddress((void**)&v, g_v);
    cudaGetSymbolAddress((void**)&ao, g_ao);

    cudaFuncSetAttribute(k_attn, cudaFuncAttributeMaxDynamicSharedMemorySize, SMEM_ATTN);

    // mask branch (restructured: 34.4 GFLOP -> ~0.45 GFLOP)
    k_pack<<<1024, 256>>>(memory_w, feats);
    k_gemm<<<dim3(16, 4), 256>>>(feats, fc_out_w,           nullptr, fA, 0, 0);
    k_gemm<<<dim3(16, 4), 256>>>(feats, fc_out_w + 256*256, nullptr, fB, 0, 0);
    k_conn<<<dim3(8, 128), 256>>>(fA, fB, fc_out_b, fc_cat_w, fc_cat_b, gumbel_u, conn);

    // MLP
    k_gemm<<<dim3(64, 4), 256>>>(x,  mlp_w1, mlp_b1, h1, 1, 0);
    k_gemm<<<dim3(64, 4), 256>>>(h1, mlp_w2, mlp_b2, xm, 0, 0);

    // QKV (permuted store to [B,H,N,DK])
    k_gemm<<<dim3(64, 4), 256>>>(xm, wq, bq, q, 0, 1);
    k_gemm<<<dim3(64, 4), 256>>>(xm, wk, bk, k, 0, 1);
    k_gemm<<<dim3(64, 4), 256>>>(xm, wv, bv, v, 0, 1);

    // masked attention
    k_attn<<<256, 128, SMEM_ATTN>>>(q, k, v, conn, ao);

    // output projection straight into d_out
    k_gemm<<<dim3(64, 4), 256>>>(ao, out_w, out_b, (float*)d_out, 0, 0);
}